// round 6
// baseline (speedup 1.0000x reference)
#include <cuda_runtime.h>
#include <cuda_bf16.h>
#include <cstdint>
#include <math.h>

// ---------------- problem dims ----------------
#define NB 64
#define NT 512
#define ND 128
#define NH 512
#define NDS 32
#define NG4 (4 * NH)   // 2048

// ---------------- LSTM config ----------------
#define G 128          // persistent CTAs
#define TPB 256        // 8 warps
#define JPC 4          // hidden units per CTA -> 16 true z-cols -> m=32 (hi/lo)
// SMEM layout (bytes)
#define H_OFF 0                    // h' [128 rows][1024B] = 131072
#define ZB_OFF 131072              // zb[2][128][33] f32 = 33792 (aliases W' staging 32KB)
#define MB_OFF 164864              // 2 mbarriers (16B)
#define LSTM_SMEM 164992

__device__ __forceinline__ uint32_t smem_u32(const void* p) {
    uint32_t a;
    asm("{ .reg .u64 t; cvta.to.shared.u64 t, %1; cvt.u32.u64 %0, t; }" : "=r"(a) : "l"(p));
    return a;
}
__device__ __forceinline__ uint16_t bf16_bits(float f) {
    return __bfloat16_as_ushort(__float2bfloat16(f));
}
__device__ __forceinline__ float bf16_val(float f) {
    return __bfloat162float(__float2bfloat16(f));
}
__device__ __forceinline__ uint16_t bf16_lo(float f) {
    return bf16_bits(f - bf16_val(f));
}
__device__ __forceinline__ float sigmoidf_(float x) { return 1.f / (1.f + expf(-x)); }

__device__ __forceinline__ uint4 pack_hi8(float4 a, float4 b) {
    uint4 r;
    r.x = (uint32_t)bf16_bits(a.x) | ((uint32_t)bf16_bits(a.y) << 16);
    r.y = (uint32_t)bf16_bits(a.z) | ((uint32_t)bf16_bits(a.w) << 16);
    r.z = (uint32_t)bf16_bits(b.x) | ((uint32_t)bf16_bits(b.y) << 16);
    r.w = (uint32_t)bf16_bits(b.z) | ((uint32_t)bf16_bits(b.w) << 16);
    return r;
}
__device__ __forceinline__ uint4 pack_lo8(float4 a, float4 b) {
    uint4 r;
    r.x = (uint32_t)bf16_lo(a.x) | ((uint32_t)bf16_lo(a.y) << 16);
    r.y = (uint32_t)bf16_lo(a.z) | ((uint32_t)bf16_lo(a.w) << 16);
    r.z = (uint32_t)bf16_lo(b.x) | ((uint32_t)bf16_lo(b.y) << 16);
    r.w = (uint32_t)bf16_lo(b.z) | ((uint32_t)bf16_lo(b.w) << 16);
    return r;
}

#define LDSM_X4(r0, r1, r2, r3, addr) \
    asm volatile("ldmatrix.sync.aligned.m8n8.x4.shared.b16 {%0,%1,%2,%3}, [%4];" \
        : "=r"(r0), "=r"(r1), "=r"(r2), "=r"(r3) : "r"(addr))

#define MMA_BF16(c, a0, a1, a2, a3, b0, b1) \
    asm volatile("mma.sync.aligned.m16n8k16.row.col.f32.bf16.bf16.f32 " \
        "{%0,%1,%2,%3}, {%4,%5,%6,%7}, {%8,%9}, {%0,%1,%2,%3};" \
        : "+f"((c)[0]), "+f"((c)[1]), "+f"((c)[2]), "+f"((c)[3]) \
        : "r"(a0), "r"(a1), "r"(a2), "r"(a3), "r"(b0), "r"(b1))

#define CP16(dst, src) \
    asm volatile("cp.async.cg.shared.global [%0], [%1], 16;" :: "r"(dst), "l"(src))
#define CP_COMMIT() asm volatile("cp.async.commit_group;" ::: "memory")
#define CP_WAIT(n)  asm volatile("cp.async.wait_group %0;" :: "n"(n) : "memory")
#define CP_MBAR_ARRIVE(mbar) \
    asm volatile("cp.async.mbarrier.arrive.noinc.shared.b64 [%0];" \
                 :: "r"((uint32_t)(mbar)) : "memory")
#define MBARRIER_INIT(mbar, cnt) \
    asm volatile("mbarrier.init.shared.b64 [%0], %1;" :: "r"((uint32_t)(mbar)), "r"((uint32_t)(cnt)) : "memory")
#define MBARRIER_WAIT_PARITY(mbar, par) do { \
    uint32_t _m = (uint32_t)(mbar); uint32_t _p = (uint32_t)(par); uint32_t _d; \
    asm volatile("{\n\t.reg .pred p;\n\t" \
        "mbarrier.try_wait.parity.acquire.cta.shared::cta.b64 p, [%1], %2;\n\t" \
        "selp.b32 %0, 1, 0, p;\n\t}" : "=r"(_d) : "r"(_m), "r"(_p) : "memory"); \
    if (!_d) { \
        asm volatile("{\n\t.reg .pred P1;\n\t" \
            "WL_%=:\n\t" \
            "mbarrier.try_wait.parity.acquire.cta.shared::cta.b64 P1, [%0], %1, 0x989680;\n\t" \
            "@P1 bra.uni WD_%=;\n\t" \
            "bra.uni WL_%=;\n\t" \
            "WD_%=:\n\t}" :: "r"(_m), "r"(_p) : "memory"); \
    } } while (0)

// ---------------- global scratch ----------------
__device__ __nv_bfloat16 g_hh[NB][NH];          // h hi
__device__ __nv_bfloat16 g_hl[NB][NH];          // h lo
__device__ __nv_bfloat16 g_wt[2 * NG4][ND];     // wk transposed, hi rows 0-2047, lo 2048-4095
__device__ float g_xw[NT][NG4][NB];             // x@Wk + bias
__device__ float g_hs[NT][NH][NB];              // hidden states for dense
__device__ unsigned int g_bar;

__global__ void init_kernel() {
    int idx = blockIdx.x * blockDim.x + threadIdx.x;
    if (idx == 0) g_bar = 0u;
    uint32_t* ph = reinterpret_cast<uint32_t*>(&g_hh[0][0]);
    uint32_t* pl = reinterpret_cast<uint32_t*>(&g_hl[0][0]);
    for (int i = idx; i < NB * NH / 2; i += gridDim.x * blockDim.x) {
        ph[i] = 0u; pl[i] = 0u;
    }
}

// ---- one-time: transpose + bf16 hi/lo split of wk into g_wt ----
__global__ void wbf_kernel(const float* __restrict__ wk) {
    int n = blockIdx.x;          // 0..4095
    int k = threadIdx.x;         // 0..127
    float w = wk[(size_t)k * NG4 + (n & (NG4 - 1))];
    g_wt[n][k] = (n < NG4) ? __ushort_as_bfloat16(bf16_bits(w))
                           : __ushort_as_bfloat16(bf16_lo(w));
}

// =====================================================================
// XW kernel (unchanged from R5): g_xw[t][col][b] = x@wk + bias
// =====================================================================
#define XA_OFF 0           // [128][256B] = 32768
#define XB_OFF 32768       // [128][256B] = 32768
#define XZ_OFF 65536       // zb[2][128][65] f32 = 66560
#define XW_SMEM 132096

__global__ void __launch_bounds__(256, 1) xw_kernel(
    const float* __restrict__ x, const float* __restrict__ bias)
{
    extern __shared__ char smem[];
    const uint32_t sbu = smem_u32(smem);
    float* zb = reinterpret_cast<float*>(smem + XZ_OFF);
    const int tid = threadIdx.x, wid = tid >> 5, lane = tid & 31;
    const int t = blockIdx.x;
    const int s7 = lane & 7;

    for (int i = tid; i < 64 * 16; i += 256) {
        int b = i >> 4, cs = i & 15;
        const float4* xp = reinterpret_cast<const float4*>(
            x + ((size_t)b * NT + t) * ND + cs * 8);
        float4 x0 = xp[0], x1 = xp[1];
        *reinterpret_cast<uint4*>(smem + XA_OFF + b * 256 + ((cs ^ (b & 7)) << 4))
            = pack_hi8(x0, x1);
        int rl = b + 64;
        *reinterpret_cast<uint4*>(smem + XA_OFF + rl * 256 + ((cs ^ (rl & 7)) << 4))
            = pack_lo8(x0, x1);
    }
    __syncthreads();

    const int mslice = wid & 3, whalf = wid >> 2;
    uint32_t ar[8][2][4];
    {
        int row8 = ((lane >> 3) & 1) * 8 + s7;
        int acb = lane >> 4;
        #pragma unroll
        for (int ks = 0; ks < 8; ks++)
            #pragma unroll
            for (int mf = 0; mf < 2; mf++) {
                int row = mslice * 32 + mf * 16 + row8;
                uint32_t addr = sbu + XA_OFF + row * 256 +
                    (((ks * 2 + acb) ^ (row & 7)) << 4);
                LDSM_X4(ar[ks][mf][0], ar[ks][mf][1], ar[ks][mf][2], ar[ks][mf][3], addr);
            }
    }

    const int browl = ((lane >> 4) << 3) + s7;
    const int bcb = (lane >> 3) & 1;

    for (int cb = 0; cb < 32; cb++) {
        #pragma unroll
        for (int it = 0; it < 8; it++) {
            int i = it * 256 + tid;
            int row = i >> 4, cpi = i & 15;
            const __nv_bfloat16* src = (row < 64)
                ? &g_wt[cb * 64 + row][cpi * 8]
                : &g_wt[NG4 + cb * 64 + (row - 64)][cpi * 8];
            uint32_t dst = sbu + XB_OFF + row * 256 + ((cpi ^ (row & 7)) << 4);
            CP16(dst, src);
        }
        CP_COMMIT();
        CP_WAIT(0);
        __syncthreads();

        float acc[2][8][4];
        #pragma unroll
        for (int mf = 0; mf < 2; mf++)
            #pragma unroll
            for (int nf = 0; nf < 8; nf++)
                #pragma unroll
                for (int q = 0; q < 4; q++) acc[mf][nf][q] = 0.f;

        #pragma unroll
        for (int ks = 0; ks < 8; ks++) {
            #pragma unroll
            for (int q = 0; q < 4; q++) {
                int rowb = whalf * 64 + q * 16 + browl;
                uint32_t baddr = sbu + XB_OFF + rowb * 256 +
                    (((ks * 2 + bcb) ^ s7) << 4);
                uint32_t b0, b1, b2, b3;
                LDSM_X4(b0, b1, b2, b3, baddr);
                #pragma unroll
                for (int mf = 0; mf < 2; mf++) {
                    MMA_BF16(acc[mf][2 * q],     ar[ks][mf][0], ar[ks][mf][1],
                             ar[ks][mf][2], ar[ks][mf][3], b0, b1);
                    MMA_BF16(acc[mf][2 * q + 1], ar[ks][mf][0], ar[ks][mf][1],
                             ar[ks][mf][2], ar[ks][mf][3], b2, b3);
                }
            }
        }

        #pragma unroll
        for (int mf = 0; mf < 2; mf++)
            #pragma unroll
            for (int nf = 0; nf < 8; nf++) {
                int m = mslice * 32 + mf * 16 + (lane >> 2);
                int c = nf * 8 + 2 * (lane & 3);
                float* zp = zb + (size_t)(whalf * 128 + m) * 65 + c;
                zp[0] = acc[mf][nf][0];
                zp[1] = acc[mf][nf][1];
                zp[8 * 65] = acc[mf][nf][2];
                zp[8 * 65 + 1] = acc[mf][nf][3];
            }
        __syncthreads();

        for (int i = tid; i < 64 * 64; i += 256) {
            int b = i & 63, c = i >> 6;
            float z = zb[(size_t)b * 65 + c] + zb[(size_t)(128 + b) * 65 + c]
                    + zb[(size_t)(b + 64) * 65 + c] + zb[(size_t)(128 + b + 64) * 65 + c]
                    + bias[cb * 64 + c];
            g_xw[t][cb * 64 + c][b] = z;
        }
        __syncthreads();
    }
}

// =====================================================================
// Persistent LSTM. A = W'^T (static regs), B = h'. Per-khalf mbarrier
// completion: the two k-half MMA pipelines run concurrently.
// =====================================================================
__global__ void __launch_bounds__(TPB, 1) lstm_kernel(
    const float* __restrict__ wr,
    float* __restrict__ out_h, float* __restrict__ out_c)
{
    extern __shared__ char smem[];
    const uint32_t sbu = smem_u32(smem);
    float* zb = reinterpret_cast<float*>(smem + ZB_OFF);   // [2][128][33]
    const uint32_t mb01 = sbu + MB_OFF, mb23 = sbu + MB_OFF + 8;

    const int tid = threadIdx.x;
    const int wid = tid >> 5, lane = tid & 31;
    const int j0 = blockIdx.x * JPC;
    const int s7 = lane & 7;
    const int khalf = wid >> 2, ngrp = wid & 3;

    if (tid == 0) {
        MBARRIER_INIT(mb01, TPB);
        MBARRIER_INIT(mb23, TPB);
    }

    // ---- W'^T staging at ZB_OFF: rows m 0-15 = hi, 16-31 = lo ----
    for (int i = tid; i < 32 * NH; i += TPB) {
        int m = i & 31, k = i >> 5;
        int c = m & 15, gate = c >> 2, jj = c & 3;
        float w = wr[(size_t)k * NG4 + gate * NH + j0 + jj];
        uint16_t bv = (m < 16) ? bf16_bits(w) : bf16_lo(w);
        *reinterpret_cast<uint16_t*>(smem + ZB_OFF + m * 1024 +
            ((((k >> 3) ^ (m & 7)) << 4) | ((k & 7) << 1))) = bv;
    }
    __syncthreads();

    // ---- a-frags (static, 128 regs): warp's k-range = khalf*256 ----
    uint32_t ar[16][2][4];
    {
        int row8 = ((lane >> 3) & 1) * 8 + s7;
        int acb = lane >> 4;
        #pragma unroll
        for (int ks = 0; ks < 16; ks++)
            #pragma unroll
            for (int mf = 0; mf < 2; mf++) {
                int row = mf * 16 + row8;
                int chunk = khalf * 32 + ks * 2 + acb;
                uint32_t addr = sbu + ZB_OFF + row * 1024 +
                    ((chunk ^ (row & 7)) << 4);
                LDSM_X4(ar[ks][mf][0], ar[ks][mf][1], ar[ks][mf][2], ar[ks][mf][3], addr);
            }
    }
    __syncthreads();

    const int gb = tid & 63;
    const int gj = (tid >> 6) & 3;
    float c_state = 0.f;

    const int browl = ((lane >> 4) << 3) + s7;
    const int bcb = (lane >> 3) & 1;
    const uint32_t bbase0 = sbu + H_OFF + (ngrp * 32 + browl) * 1024;
    const uint32_t bbase1 = bbase0 + 16 * 1024;

    for (int t = 0; t < NT; t++) {
        // prefetch xw (hidden under h stream)
        float xwv[4];
        #pragma unroll
        for (int g = 0; g < 4; g++)
            xwv[g] = __ldcg(&g_xw[t][g * NH + j0 + gj][gb]);

        // ---- stream h': chunks 0,1 -> mb01; chunks 2,3 -> mb23 ----
        #pragma unroll
        for (int ch = 0; ch < 2; ch++) {
            #pragma unroll
            for (int it = 0; it < 8; it++) {
                int i = it * 256 + tid;
                int row = i >> 4, cpi = i & 15;
                const __nv_bfloat16* src = (row < 64)
                    ? &g_hh[row][ch * 128 + cpi * 8]
                    : &g_hl[row - 64][ch * 128 + cpi * 8];
                int gch = ch * 16 + cpi;
                uint32_t dst = sbu + H_OFF + row * 1024 + ((gch ^ (row & 7)) << 4);
                CP16(dst, src);
            }
        }
        CP_MBAR_ARRIVE(mb01);
        #pragma unroll
        for (int ch = 2; ch < 4; ch++) {
            #pragma unroll
            for (int it = 0; it < 8; it++) {
                int i = it * 256 + tid;
                int row = i >> 4, cpi = i & 15;
                const __nv_bfloat16* src = (row < 64)
                    ? &g_hh[row][ch * 128 + cpi * 8]
                    : &g_hl[row - 64][ch * 128 + cpi * 8];
                int gch = ch * 16 + cpi;
                uint32_t dst = sbu + H_OFF + row * 1024 + ((gch ^ (row & 7)) << 4);
                CP16(dst, src);
            }
        }
        CP_MBAR_ARRIVE(mb23);

        float acc[2][4][4];
        #pragma unroll
        for (int mf = 0; mf < 2; mf++)
            #pragma unroll
            for (int nf = 0; nf < 4; nf++)
                #pragma unroll
                for (int q = 0; q < 4; q++) acc[mf][nf][q] = 0.f;

        if (khalf == 0) {
            MBARRIER_WAIT_PARITY(mb01, t & 1);
            #pragma unroll
            for (int ks = 0; ks < 16; ks++) {
                int chunk = ks * 2 + bcb;
                uint32_t off = ((chunk ^ s7) << 4);
                uint32_t b00, b01, b10, b11, b20, b21, b30, b31;
                LDSM_X4(b00, b01, b10, b11, bbase0 + off);
                LDSM_X4(b20, b21, b30, b31, bbase1 + off);
                #pragma unroll
                for (int mf = 0; mf < 2; mf++) {
                    MMA_BF16(acc[mf][0], ar[ks][mf][0], ar[ks][mf][1], ar[ks][mf][2], ar[ks][mf][3], b00, b01);
                    MMA_BF16(acc[mf][1], ar[ks][mf][0], ar[ks][mf][1], ar[ks][mf][2], ar[ks][mf][3], b10, b11);
                    MMA_BF16(acc[mf][2], ar[ks][mf][0], ar[ks][mf][1], ar[ks][mf][2], ar[ks][mf][3], b20, b21);
                    MMA_BF16(acc[mf][3], ar[ks][mf][0], ar[ks][mf][1], ar[ks][mf][2], ar[ks][mf][3], b30, b31);
                }
            }
        } else {
            MBARRIER_WAIT_PARITY(mb23, t & 1);
            #pragma unroll
            for (int ks = 0; ks < 16; ks++) {
                int chunk = 32 + ks * 2 + bcb;
                uint32_t off = ((chunk ^ s7) << 4);
                uint32_t b00, b01, b10, b11, b20, b21, b30, b31;
                LDSM_X4(b00, b01, b10, b11, bbase0 + off);
                LDSM_X4(b20, b21, b30, b31, bbase1 + off);
                #pragma unroll
                for (int mf = 0; mf < 2; mf++) {
                    MMA_BF16(acc[mf][0], ar[ks][mf][0], ar[ks][mf][1], ar[ks][mf][2], ar[ks][mf][3], b00, b01);
                    MMA_BF16(acc[mf][1], ar[ks][mf][0], ar[ks][mf][1], ar[ks][mf][2], ar[ks][mf][3], b10, b11);
                    MMA_BF16(acc[mf][2], ar[ks][mf][0], ar[ks][mf][1], ar[ks][mf][2], ar[ks][mf][3], b20, b21);
                    MMA_BF16(acc[mf][3], ar[ks][mf][0], ar[ks][mf][1], ar[ks][mf][2], ar[ks][mf][3], b30, b31);
                }
            }
        }

        // epilogue: zb[khalf][n][m]
        #pragma unroll
        for (int mf = 0; mf < 2; mf++)
            #pragma unroll
            for (int nf = 0; nf < 4; nf++) {
                int m = mf * 16 + (lane >> 2);
                int n = ngrp * 32 + nf * 8 + 2 * (lane & 3);
                float* zp = zb + (size_t)(khalf * 128 + n) * 33 + m;
                zp[0]      = acc[mf][nf][0];
                zp[33]     = acc[mf][nf][1];
                zp[8]      = acc[mf][nf][2];
                zp[33 + 8] = acc[mf][nf][3];
            }
        __syncthreads();

        // ---- gates ----
        {
            float z[4];
            #pragma unroll
            for (int g = 0; g < 4; g++) {
                int c = g * 4 + gj;
                float s = xwv[g];
                #pragma unroll
                for (int kh = 0; kh < 2; kh++) {
                    const float* z0 = zb + (size_t)(kh * 128 + gb) * 33;
                    const float* z1 = zb + (size_t)(kh * 128 + gb + 64) * 33;
                    s += z0[c] + z0[c + 16] + z1[c] + z1[c + 16];
                }
                z[g] = s;
            }
            float ig = sigmoidf_(z[0]);
            float fg = sigmoidf_(z[1]);
            float gv = tanhf(z[2]);
            float og = sigmoidf_(z[3]);
            c_state = fg * c_state + ig * gv;
            float hv = og * tanhf(c_state);
            int row = j0 + gj;
            __nv_bfloat16 hh = __float2bfloat16(hv);
            g_hh[gb][row] = hh;
            g_hl[gb][row] = __float2bfloat16(hv - __bfloat162float(hh));
            g_hs[t][row][gb] = hv;
            if (t == NT - 1) {
                out_h[(size_t)gb * NH + row] = hv;
                out_c[(size_t)gb * NH + row] = c_state;
            }
        }
        __syncthreads();

        // ---- grid barrier (monotonic atomic counter) ----
        if (t < NT - 1) {
            if (tid == 0) {
                __threadfence();
                atomicAdd(&g_bar, 1u);
                unsigned int target = (unsigned int)G * (unsigned int)(t + 1);
                unsigned int cur;
                do {
                    asm volatile("ld.volatile.global.u32 %0, [%1];" : "=r"(cur) : "l"(&g_bar));
                } while (cur < target);
                __threadfence();
            }
            __syncthreads();
        }
    }
}

// ---------------- Dense(32, tanh) over all timesteps ----------------
#define DTPB 256
__global__ void __launch_bounds__(DTPB, 1) dense_kernel(
    const float* __restrict__ dw, const float* __restrict__ db,
    float* __restrict__ out)
{
    extern __shared__ float smemf[];
    float* hsm = smemf;
    float* wsm = smemf + NH * NB;
    int t = blockIdx.x, tid = threadIdx.x;
    {
        const float4* src = reinterpret_cast<const float4*>(&g_hs[t][0][0]);
        float4* dst = reinterpret_cast<float4*>(hsm);
        for (int i = tid; i < NH * NB / 4; i += DTPB) dst[i] = src[i];
        const float4* ws = reinterpret_cast<const float4*>(dw);
        float4* wd = reinterpret_cast<float4*>(wsm);
        for (int i = tid; i < NH * NDS / 4; i += DTPB) wd[i] = ws[i];
    }
    __syncthreads();

    int bg = tid & 15, dg = tid >> 4;
    float acc[4][2];
    #pragma unroll
    for (int bi = 0; bi < 4; bi++) { acc[bi][0] = 0.f; acc[bi][1] = 0.f; }
    #pragma unroll 4
    for (int k = 0; k < NH; k++) {
        float4 hv = *reinterpret_cast<const float4*>(&hsm[k * NB + bg * 4]);
        float2 wv = *reinterpret_cast<const float2*>(&wsm[k * NDS + dg * 2]);
        float hvv[4] = {hv.x, hv.y, hv.z, hv.w};
        #pragma unroll
        for (int bi = 0; bi < 4; bi++) {
            acc[bi][0] += hvv[bi] * wv.x;
            acc[bi][1] += hvv[bi] * wv.y;
        }
    }
    float b0 = db[dg * 2], b1 = db[dg * 2 + 1];
    #pragma unroll
    for (int bi = 0; bi < 4; bi++) {
        int b = bg * 4 + bi;
        size_t base = (size_t)b * NT * NDS + (size_t)t * NDS + dg * 2;
        out[base]     = tanhf(acc[bi][0] + b0);
        out[base + 1] = tanhf(acc[bi][1] + b1);
    }
}

#define DENSE_SMEM ((NH * NB + NH * NDS) * 4)

extern "C" void kernel_launch(void* const* d_in, const int* in_sizes, int n_in,
                              void* d_out, int out_size) {
    const float* x    = (const float*)d_in[0];
    const float* wk   = (const float*)d_in[1];
    const float* wr   = (const float*)d_in[2];
    const float* bias = (const float*)d_in[3];
    const float* dw   = (const float*)d_in[4];
    const float* db   = (const float*)d_in[5];
    float* out   = (float*)d_out;
    float* out_h = out + (size_t)NB * NT * NDS;
    float* out_c = out_h + (size_t)NB * NH;

    cudaFuncSetAttribute(xw_kernel,
                         cudaFuncAttributeMaxDynamicSharedMemorySize, XW_SMEM);
    cudaFuncSetAttribute(lstm_kernel,
                         cudaFuncAttributeMaxDynamicSharedMemorySize, LSTM_SMEM);
    cudaFuncSetAttribute(dense_kernel,
                         cudaFuncAttributeMaxDynamicSharedMemorySize, DENSE_SMEM);

    init_kernel<<<64, 256>>>();                          // 0
    wbf_kernel<<<2 * NG4, ND>>>(wk);                     // 1
    xw_kernel<<<NT, 256, XW_SMEM>>>(x, bias);            // 2
    lstm_kernel<<<G, TPB, LSTM_SMEM>>>(wr, out_h, out_c);// 3  <- profiled slot
    dense_kernel<<<NT, DTPB, DENSE_SMEM>>>(dw, db, out); // 4
}

// round 7
// speedup vs baseline: 1.1020x; 1.1020x over previous
#include <cuda_runtime.h>
#include <cuda_bf16.h>
#include <cstdint>
#include <math.h>

// ---------------- problem dims ----------------
#define NB 64
#define NT 512
#define ND 128
#define NH 512
#define NDS 32
#define NG4 (4 * NH)   // 2048

// ---------------- LSTM config ----------------
#define G 128          // persistent CTAs
#define TPB 256        // 8 warps
#define JPC 4          // hidden units per CTA -> 16 true z-cols
// SMEM layout (bytes)
#define H_OFF 0                    // h' [128 rows][1024B] = 131072
#define ZB_OFF 131072              // W' staging 32KB, then zhi/zlo (13KB)
#define MB_OFF 163840              // 4 mbarriers
#define LSTM_SMEM 163904

__device__ __forceinline__ uint32_t smem_u32(const void* p) {
    uint32_t a;
    asm("{ .reg .u64 t; cvta.to.shared.u64 t, %1; cvt.u32.u64 %0, t; }" : "=r"(a) : "l"(p));
    return a;
}
__device__ __forceinline__ uint16_t bf16_bits(float f) {
    return __bfloat16_as_ushort(__float2bfloat16(f));
}
__device__ __forceinline__ float bf16_val(float f) {
    return __bfloat162float(__float2bfloat16(f));
}
__device__ __forceinline__ uint16_t bf16_lo(float f) {
    return bf16_bits(f - bf16_val(f));
}
__device__ __forceinline__ float sigmoidf_(float x) { return 1.f / (1.f + expf(-x)); }

__device__ __forceinline__ uint4 pack_hi8(float4 a, float4 b) {
    uint4 r;
    r.x = (uint32_t)bf16_bits(a.x) | ((uint32_t)bf16_bits(a.y) << 16);
    r.y = (uint32_t)bf16_bits(a.z) | ((uint32_t)bf16_bits(a.w) << 16);
    r.z = (uint32_t)bf16_bits(b.x) | ((uint32_t)bf16_bits(b.y) << 16);
    r.w = (uint32_t)bf16_bits(b.z) | ((uint32_t)bf16_bits(b.w) << 16);
    return r;
}
__device__ __forceinline__ uint4 pack_lo8(float4 a, float4 b) {
    uint4 r;
    r.x = (uint32_t)bf16_lo(a.x) | ((uint32_t)bf16_lo(a.y) << 16);
    r.y = (uint32_t)bf16_lo(a.z) | ((uint32_t)bf16_lo(a.w) << 16);
    r.z = (uint32_t)bf16_lo(b.x) | ((uint32_t)bf16_lo(b.y) << 16);
    r.w = (uint32_t)bf16_lo(b.z) | ((uint32_t)bf16_lo(b.w) << 16);
    return r;
}

#define LDSM_X4(r0, r1, r2, r3, addr) \
    asm volatile("ldmatrix.sync.aligned.m8n8.x4.shared.b16 {%0,%1,%2,%3}, [%4];" \
        : "=r"(r0), "=r"(r1), "=r"(r2), "=r"(r3) : "r"(addr))

#define MMA_BF16(c, a0, a1, a2, a3, b0, b1) \
    asm volatile("mma.sync.aligned.m16n8k16.row.col.f32.bf16.bf16.f32 " \
        "{%0,%1,%2,%3}, {%4,%5,%6,%7}, {%8,%9}, {%0,%1,%2,%3};" \
        : "+f"((c)[0]), "+f"((c)[1]), "+f"((c)[2]), "+f"((c)[3]) \
        : "r"(a0), "r"(a1), "r"(a2), "r"(a3), "r"(b0), "r"(b1))

#define CP16(dst, src) \
    asm volatile("cp.async.cg.shared.global [%0], [%1], 16;" :: "r"(dst), "l"(src))
#define CP_COMMIT() asm volatile("cp.async.commit_group;" ::: "memory")
#define CP_WAIT(n)  asm volatile("cp.async.wait_group %0;" :: "n"(n) : "memory")
#define CP_MBAR_ARRIVE(mbar) \
    asm volatile("cp.async.mbarrier.arrive.noinc.shared.b64 [%0];" \
                 :: "r"((uint32_t)(mbar)) : "memory")
#define MBARRIER_INIT(mbar, cnt) \
    asm volatile("mbarrier.init.shared.b64 [%0], %1;" :: "r"((uint32_t)(mbar)), "r"((uint32_t)(cnt)) : "memory")
#define MBARRIER_WAIT_PARITY(mbar, par) do { \
    uint32_t _m = (uint32_t)(mbar); uint32_t _p = (uint32_t)(par); uint32_t _d; \
    asm volatile("{\n\t.reg .pred p;\n\t" \
        "mbarrier.try_wait.parity.acquire.cta.shared::cta.b64 p, [%1], %2;\n\t" \
        "selp.b32 %0, 1, 0, p;\n\t}" : "=r"(_d) : "r"(_m), "r"(_p) : "memory"); \
    if (!_d) { \
        asm volatile("{\n\t.reg .pred P1;\n\t" \
            "WL_%=:\n\t" \
            "mbarrier.try_wait.parity.acquire.cta.shared::cta.b64 P1, [%0], %1, 0x989680;\n\t" \
            "@P1 bra.uni WD_%=;\n\t" \
            "bra.uni WL_%=;\n\t" \
            "WD_%=:\n\t}" :: "r"(_m), "r"(_p) : "memory"); \
    } } while (0)

// ---------------- global scratch ----------------
__device__ __nv_bfloat16 g_hh[NB][NH];          // h hi
__device__ __nv_bfloat16 g_hl[NB][NH];          // h lo
__device__ __nv_bfloat16 g_wt[2 * NG4][ND];     // wk transposed hi/lo
__device__ float g_xw[NT][NG4][NB];             // x@Wk + bias
__device__ float g_hs[NT][NH][NB];              // hidden states for dense
__device__ unsigned int g_bar;

__global__ void init_kernel() {
    int idx = blockIdx.x * blockDim.x + threadIdx.x;
    if (idx == 0) g_bar = 0u;
    uint32_t* ph = reinterpret_cast<uint32_t*>(&g_hh[0][0]);
    uint32_t* pl = reinterpret_cast<uint32_t*>(&g_hl[0][0]);
    for (int i = idx; i < NB * NH / 2; i += gridDim.x * blockDim.x) {
        ph[i] = 0u; pl[i] = 0u;
    }
}

// ---- one-time: transpose + bf16 hi/lo split of wk ----
__global__ void wbf_kernel(const float* __restrict__ wk) {
    int n = blockIdx.x;
    int k = threadIdx.x;
    float w = wk[(size_t)k * NG4 + (n & (NG4 - 1))];
    g_wt[n][k] = (n < NG4) ? __ushort_as_bfloat16(bf16_bits(w))
                           : __ushort_as_bfloat16(bf16_lo(w));
}

// =====================================================================
// XW kernel (proven in R5/R6): g_xw[t][col][b] = x@wk + bias
// =====================================================================
#define XA_OFF 0
#define XB_OFF 32768
#define XZ_OFF 65536
#define XW_SMEM 132096

__global__ void __launch_bounds__(256, 1) xw_kernel(
    const float* __restrict__ x, const float* __restrict__ bias)
{
    extern __shared__ char smem[];
    const uint32_t sbu = smem_u32(smem);
    float* zb = reinterpret_cast<float*>(smem + XZ_OFF);
    const int tid = threadIdx.x, wid = tid >> 5, lane = tid & 31;
    const int t = blockIdx.x;
    const int s7 = lane & 7;

    for (int i = tid; i < 64 * 16; i += 256) {
        int b = i >> 4, cs = i & 15;
        const float4* xp = reinterpret_cast<const float4*>(
            x + ((size_t)b * NT + t) * ND + cs * 8);
        float4 x0 = xp[0], x1 = xp[1];
        *reinterpret_cast<uint4*>(smem + XA_OFF + b * 256 + ((cs ^ (b & 7)) << 4))
            = pack_hi8(x0, x1);
        int rl = b + 64;
        *reinterpret_cast<uint4*>(smem + XA_OFF + rl * 256 + ((cs ^ (rl & 7)) << 4))
            = pack_lo8(x0, x1);
    }
    __syncthreads();

    const int mslice = wid & 3, whalf = wid >> 2;
    uint32_t ar[8][2][4];
    {
        int row8 = ((lane >> 3) & 1) * 8 + s7;
        int acb = lane >> 4;
        #pragma unroll
        for (int ks = 0; ks < 8; ks++)
            #pragma unroll
            for (int mf = 0; mf < 2; mf++) {
                int row = mslice * 32 + mf * 16 + row8;
                uint32_t addr = sbu + XA_OFF + row * 256 +
                    (((ks * 2 + acb) ^ (row & 7)) << 4);
                LDSM_X4(ar[ks][mf][0], ar[ks][mf][1], ar[ks][mf][2], ar[ks][mf][3], addr);
            }
    }

    const int browl = ((lane >> 4) << 3) + s7;
    const int bcb = (lane >> 3) & 1;

    for (int cb = 0; cb < 32; cb++) {
        #pragma unroll
        for (int it = 0; it < 8; it++) {
            int i = it * 256 + tid;
            int row = i >> 4, cpi = i & 15;
            const __nv_bfloat16* src = (row < 64)
                ? &g_wt[cb * 64 + row][cpi * 8]
                : &g_wt[NG4 + cb * 64 + (row - 64)][cpi * 8];
            uint32_t dst = sbu + XB_OFF + row * 256 + ((cpi ^ (row & 7)) << 4);
            CP16(dst, src);
        }
        CP_COMMIT();
        CP_WAIT(0);
        __syncthreads();

        float acc[2][8][4];
        #pragma unroll
        for (int mf = 0; mf < 2; mf++)
            #pragma unroll
            for (int nf = 0; nf < 8; nf++)
                #pragma unroll
                for (int q = 0; q < 4; q++) acc[mf][nf][q] = 0.f;

        #pragma unroll
        for (int ks = 0; ks < 8; ks++) {
            #pragma unroll
            for (int q = 0; q < 4; q++) {
                int rowb = whalf * 64 + q * 16 + browl;
                uint32_t baddr = sbu + XB_OFF + rowb * 256 +
                    (((ks * 2 + bcb) ^ s7) << 4);
                uint32_t b0, b1, b2, b3;
                LDSM_X4(b0, b1, b2, b3, baddr);
                #pragma unroll
                for (int mf = 0; mf < 2; mf++) {
                    MMA_BF16(acc[mf][2 * q],     ar[ks][mf][0], ar[ks][mf][1],
                             ar[ks][mf][2], ar[ks][mf][3], b0, b1);
                    MMA_BF16(acc[mf][2 * q + 1], ar[ks][mf][0], ar[ks][mf][1],
                             ar[ks][mf][2], ar[ks][mf][3], b2, b3);
                }
            }
        }

        #pragma unroll
        for (int mf = 0; mf < 2; mf++)
            #pragma unroll
            for (int nf = 0; nf < 8; nf++) {
                int m = mslice * 32 + mf * 16 + (lane >> 2);
                int c = nf * 8 + 2 * (lane & 3);
                float* zp = zb + (size_t)(whalf * 128 + m) * 65 + c;
                zp[0] = acc[mf][nf][0];
                zp[1] = acc[mf][nf][1];
                zp[8 * 65] = acc[mf][nf][2];
                zp[8 * 65 + 1] = acc[mf][nf][3];
            }
        __syncthreads();

        for (int i = tid; i < 64 * 64; i += 256) {
            int b = i & 63, c = i >> 6;
            float z = zb[(size_t)b * 65 + c] + zb[(size_t)(128 + b) * 65 + c]
                    + zb[(size_t)(b + 64) * 65 + c] + zb[(size_t)(128 + b + 64) * 65 + c]
                    + bias[cb * 64 + c];
            g_xw[t][cb * 64 + c][b] = z;
        }
        __syncthreads();
    }
}

// =====================================================================
// Persistent LSTM. Warps 0-3: Whi(m16) x n128 (hhi+hlo); warps 4-7:
// Wlo(m16) x n64 (hhi). Full k=512 of W in regs per warp (128 regs) ->
// all warps consume h-chunks in arrival order (4 chunk mbarriers).
// =====================================================================
__global__ void __launch_bounds__(TPB, 1) lstm_kernel(
    const float* __restrict__ wr,
    float* __restrict__ out_h, float* __restrict__ out_c)
{
    extern __shared__ char smem[];
    const uint32_t sbu = smem_u32(smem);
    float* zhi = reinterpret_cast<float*>(smem + ZB_OFF);   // [128][17]
    float* zlo = zhi + 128 * 17;                            // [64][17]

    const int tid = threadIdx.x;
    const int wid = tid >> 5, lane = tid & 31;
    const int j0 = blockIdx.x * JPC;
    const int s7 = lane & 7;
    const bool hiW = (wid < 4);

    if (tid == 0) {
        #pragma unroll
        for (int c = 0; c < 4; c++) MBARRIER_INIT(sbu + MB_OFF + 8 * c, TPB);
    }

    // ---- W' staging at ZB_OFF: rows m 0-15 = Whi, 16-31 = Wlo ----
    for (int i = tid; i < 32 * NH; i += TPB) {
        int m = i & 31, k = i >> 5;
        int c = m & 15, gate = c >> 2, jj = c & 3;
        float w = wr[(size_t)k * NG4 + gate * NH + j0 + jj];
        uint16_t bv = (m < 16) ? bf16_bits(w) : bf16_lo(w);
        *reinterpret_cast<uint16_t*>(smem + ZB_OFF + m * 1024 +
            ((((k >> 3) ^ (m & 7)) << 4) | ((k & 7) << 1))) = bv;
    }
    __syncthreads();

    // ---- a-frags: full k=512, m16 (Whi for w0-3, Wlo for w4-7) ----
    uint32_t ar[32][4];
    {
        int row = (hiW ? 0 : 16) + ((lane >> 3) & 1) * 8 + s7;
        int acb = lane >> 4;
        uint32_t rbase = sbu + ZB_OFF + row * 1024;
        #pragma unroll
        for (int ks = 0; ks < 32; ks++) {
            int chunk = ks * 2 + acb;
            LDSM_X4(ar[ks][0], ar[ks][1], ar[ks][2], ar[ks][3],
                    rbase + ((chunk ^ (row & 7)) << 4));
        }
    }
    __syncthreads();   // staging free; zhi/zlo reuse

    const int gb = tid & 63;
    const int gj = (tid >> 6) & 3;
    float c_state = 0.f;

    const int browl = ((lane >> 4) << 3) + s7;
    const int bcb = (lane >> 3) & 1;
    // n-slice bases: w0-3: rows [wid*32, +32); w4-7: rows [(wid-4)*16, +16)
    const uint32_t bbase0 = sbu + H_OFF +
        ((hiW ? wid * 32 : (wid - 4) * 16) + browl) * 1024;
    const uint32_t bbase1 = bbase0 + 16 * 1024;

    for (int t = 0; t < NT; t++) {
        // prefetch xw (DRAM; consumed at gates)
        float xwv[4];
        #pragma unroll
        for (int g = 0; g < 4; g++)
            xwv[g] = __ldcg(&g_xw[t][g * NH + j0 + gj][gb]);

        // ---- issue h' stream: 4 k-chunks of 128, chunk c -> mbar c ----
        #pragma unroll
        for (int ch = 0; ch < 4; ch++) {
            #pragma unroll
            for (int it = 0; it < 8; it++) {
                int i = it * 256 + tid;
                int row = i >> 4, q = i & 15;
                const __nv_bfloat16* src = (row < 64)
                    ? &g_hh[row][ch * 128 + q * 8]
                    : &g_hl[row - 64][ch * 128 + q * 8];
                int gch = ch * 16 + q;
                uint32_t dst = sbu + H_OFF + row * 1024 + ((gch ^ (row & 7)) << 4);
                CP16(dst, src);
            }
            CP_MBAR_ARRIVE(sbu + MB_OFF + 8 * ch);
        }

        float acc[4][4];
        #pragma unroll
        for (int nf = 0; nf < 4; nf++)
            #pragma unroll
            for (int q = 0; q < 4; q++) acc[nf][q] = 0.f;

        // ---- chunk-ordered MMA: all warps consume chunks as they land ----
        if (hiW) {
            #pragma unroll
            for (int c = 0; c < 4; c++) {
                MBARRIER_WAIT_PARITY(sbu + MB_OFF + 8 * c, t & 1);
                #pragma unroll
                for (int kk = 0; kk < 8; kk++) {
                    int ks = c * 8 + kk;
                    uint32_t off = (((ks * 2 + bcb) ^ s7) << 4);
                    uint32_t b00, b01, b10, b11, b20, b21, b30, b31;
                    LDSM_X4(b00, b01, b10, b11, bbase0 + off);
                    LDSM_X4(b20, b21, b30, b31, bbase1 + off);
                    MMA_BF16(acc[0], ar[ks][0], ar[ks][1], ar[ks][2], ar[ks][3], b00, b01);
                    MMA_BF16(acc[1], ar[ks][0], ar[ks][1], ar[ks][2], ar[ks][3], b10, b11);
                    MMA_BF16(acc[2], ar[ks][0], ar[ks][1], ar[ks][2], ar[ks][3], b20, b21);
                    MMA_BF16(acc[3], ar[ks][0], ar[ks][1], ar[ks][2], ar[ks][3], b30, b31);
                }
            }
        } else {
            #pragma unroll
            for (int c = 0; c < 4; c++) {
                MBARRIER_WAIT_PARITY(sbu + MB_OFF + 8 * c, t & 1);
                #pragma unroll
                for (int kk = 0; kk < 8; kk++) {
                    int ks = c * 8 + kk;
                    uint32_t off = (((ks * 2 + bcb) ^ s7) << 4);
                    uint32_t b00, b01, b10, b11;
                    LDSM_X4(b00, b01, b10, b11, bbase0 + off);
                    MMA_BF16(acc[0], ar[ks][0], ar[ks][1], ar[ks][2], ar[ks][3], b00, b01);
                    MMA_BF16(acc[1], ar[ks][0], ar[ks][1], ar[ks][2], ar[ks][3], b10, b11);
                }
            }
        }

        // ---- epilogue ----
        if (hiW) {
            #pragma unroll
            for (int nf = 0; nf < 4; nf++) {
                int m = lane >> 2;
                int n = wid * 32 + nf * 8 + 2 * (lane & 3);
                zhi[(size_t)n * 17 + m]            = acc[nf][0];
                zhi[(size_t)(n + 1) * 17 + m]      = acc[nf][1];
                zhi[(size_t)n * 17 + m + 8]        = acc[nf][2];
                zhi[(size_t)(n + 1) * 17 + m + 8]  = acc[nf][3];
            }
        } else {
            #pragma unroll
            for (int nf = 0; nf < 2; nf++) {
                int m = lane >> 2;
                int n = (wid - 4) * 16 + nf * 8 + 2 * (lane & 3);
                zlo[(size_t)n * 17 + m]            = acc[nf][0];
                zlo[(size_t)(n + 1) * 17 + m]      = acc[nf][1];
                zlo[(size_t)n * 17 + m + 8]        = acc[nf][2];
                zlo[(size_t)(n + 1) * 17 + m + 8]  = acc[nf][3];
            }
        }
        __syncthreads();

        // ---- gates: z = xw + Whi·hhi + Whi·hlo + Wlo·hhi ----
        {
            float z[4];
            #pragma unroll
            for (int g = 0; g < 4; g++) {
                int c = g * 4 + gj;
                z[g] = xwv[g] + zhi[(size_t)gb * 17 + c]
                     + zhi[(size_t)(gb + 64) * 17 + c]
                     + zlo[(size_t)gb * 17 + c];
            }
            float ig = sigmoidf_(z[0]);
            float fg = sigmoidf_(z[1]);
            float gv = tanhf(z[2]);
            float og = sigmoidf_(z[3]);
            c_state = fg * c_state + ig * gv;
            float hv = og * tanhf(c_state);
            int row = j0 + gj;
            __nv_bfloat16 hh = __float2bfloat16(hv);
            g_hh[gb][row] = hh;
            g_hl[gb][row] = __float2bfloat16(hv - __bfloat162float(hh));
            g_hs[t][row][gb] = hv;
            if (t == NT - 1) {
                out_h[(size_t)gb * NH + row] = hv;
                out_c[(size_t)gb * NH + row] = c_state;
            }
        }
        __syncthreads();

        // ---- grid barrier (monotonic atomic counter) ----
        if (t < NT - 1) {
            if (tid == 0) {
                __threadfence();
                atomicAdd(&g_bar, 1u);
                unsigned int target = (unsigned int)G * (unsigned int)(t + 1);
                unsigned int cur;
                do {
                    asm volatile("ld.volatile.global.u32 %0, [%1];" : "=r"(cur) : "l"(&g_bar));
                } while (cur < target);
                __threadfence();
            }
            __syncthreads();
        }
    }
}

// ---------------- Dense(32, tanh) over all timesteps ----------------
#define DTPB 256
__global__ void __launch_bounds__(DTPB, 1) dense_kernel(
    const float* __restrict__ dw, const float* __restrict__ db,
    float* __restrict__ out)
{
    extern __shared__ float smemf[];
    float* hsm = smemf;
    float* wsm = smemf + NH * NB;
    int t = blockIdx.x, tid = threadIdx.x;
    {
        const float4* src = reinterpret_cast<const float4*>(&g_hs[t][0][0]);
        float4* dst = reinterpret_cast<float4*>(hsm);
        for (int i = tid; i < NH * NB / 4; i += DTPB) dst[i] = src[i];
        const float4* ws = reinterpret_cast<const float4*>(dw);
        float4* wd = reinterpret_cast<float4*>(wsm);
        for (int i = tid; i < NH * NDS / 4; i += DTPB) wd[i] = ws[i];
    }
    __syncthreads();

    int bg = tid & 15, dg = tid >> 4;
    float acc[4][2];
    #pragma unroll
    for (int bi = 0; bi < 4; bi++) { acc[bi][0] = 0.f; acc[bi][1] = 0.f; }
    #pragma unroll 4
    for (int k = 0; k < NH; k++) {
        float4 hv = *reinterpret_cast<const float4*>(&hsm[k * NB + bg * 4]);
        float2 wv = *reinterpret_cast<const float2*>(&wsm[k * NDS + dg * 2]);
        float hvv[4] = {hv.x, hv.y, hv.z, hv.w};
        #pragma unroll
        for (int bi = 0; bi < 4; bi++) {
            acc[bi][0] += hvv[bi] * wv.x;
            acc[bi][1] += hvv[bi] * wv.y;
        }
    }
    float b0 = db[dg * 2], b1 = db[dg * 2 + 1];
    #pragma unroll
    for (int bi = 0; bi < 4; bi++) {
        int b = bg * 4 + bi;
        size_t base = (size_t)b * NT * NDS + (size_t)t * NDS + dg * 2;
        out[base]     = tanhf(acc[bi][0] + b0);
        out[base + 1] = tanhf(acc[bi][1] + b1);
    }
}

#define DENSE_SMEM ((NH * NB + NH * NDS) * 4)

extern "C" void kernel_launch(void* const* d_in, const int* in_sizes, int n_in,
                              void* d_out, int out_size) {
    const float* x    = (const float*)d_in[0];
    const float* wk   = (const float*)d_in[1];
    const float* wr   = (const float*)d_in[2];
    const float* bias = (const float*)d_in[3];
    const float* dw   = (const float*)d_in[4];
    const float* db   = (const float*)d_in[5];
    float* out   = (float*)d_out;
    float* out_h = out + (size_t)NB * NT * NDS;
    float* out_c = out_h + (size_t)NB * NH;

    cudaFuncSetAttribute(xw_kernel,
                         cudaFuncAttributeMaxDynamicSharedMemorySize, XW_SMEM);
    cudaFuncSetAttribute(lstm_kernel,
                         cudaFuncAttributeMaxDynamicSharedMemorySize, LSTM_SMEM);
    cudaFuncSetAttribute(dense_kernel,
                         cudaFuncAttributeMaxDynamicSharedMemorySize, DENSE_SMEM);

    init_kernel<<<64, 256>>>();                          // 0
    wbf_kernel<<<2 * NG4, ND>>>(wk);                     // 1
    xw_kernel<<<NT, 256, XW_SMEM>>>(x, bias);            // 2
    lstm_kernel<<<G, TPB, LSTM_SMEM>>>(wr, out_h, out_c);// 3  <- profiled slot
    dense_kernel<<<NT, DTPB, DENSE_SMEM>>>(dw, db, out); // 4
}